// round 3
// baseline (speedup 1.0000x reference)
#include <cuda_runtime.h>
#include <cstdint>

#define NF     51
#define UNITS  128
#define G3     384
#define TENC   50
#define NDEC   27
#define GAMMA  28
#define OUTD   102
#define KW     13056          // UNITS*OUTD
#define NW     13158
#define BTOT   8192
#define TSEQ   64
#define ROWS   64
#define RP     68             // padded row stride (floats)
#define KTOT   179            // 128 h + 51 input
#define TSP    65             // ts stride
#define CC     0.5413248546129181f

#define SMFLOATS (KTOT*RP + OUTD*TSP)

__device__ __align__(16) float g_Azr[KTOT * 128 * 2];
__device__ __align__(16) float g_Axh[NF * 128];
__device__ __align__(16) float g_Arh[UNITS * 128];
__device__ __align__(16) float g_wdec[GAMMA * NW];
__device__ __align__(16) float g_eps[NDEC * BTOT * NF];

typedef unsigned long long u64;
typedef unsigned int u32;

// ---------- f32x2 helpers ----------
__device__ __forceinline__ u64 pk2(float lo, float hi) {
    u64 r; asm("mov.b64 %0, {%1, %2};" : "=l"(r) : "f"(lo), "f"(hi)); return r;
}
__device__ __forceinline__ float2 upk2(u64 v) {
    float2 f; asm("mov.b64 {%0, %1}, %2;" : "=f"(f.x), "=f"(f.y) : "l"(v)); return f;
}
__device__ __forceinline__ void fma2(u64& d, u64 a, u64 b) {
    asm("fma.rn.f32x2 %0, %1, %2, %0;" : "+l"(d) : "l"(a), "l"(b));
}

// ---------- JAX threefry2x32 (exact) ----------
__device__ __forceinline__ uint2 tf2x32(u32 k0, u32 k1, u32 x0, u32 x1) {
    u32 k2 = k0 ^ k1 ^ 0x1BD11BDAu;
#define TFR(r) { x0 += x1; x1 = (x1 << (r)) | (x1 >> (32 - (r))); x1 ^= x0; }
    x0 += k0; x1 += k1;
    TFR(13) TFR(15) TFR(26) TFR(6)   x0 += k1; x1 += k2 + 1u;
    TFR(17) TFR(29) TFR(16) TFR(24)  x0 += k2; x1 += k0 + 2u;
    TFR(13) TFR(15) TFR(26) TFR(6)   x0 += k0; x1 += k1 + 3u;
    TFR(17) TFR(29) TFR(16) TFR(24)  x0 += k1; x1 += k2 + 4u;
    TFR(13) TFR(15) TFR(26) TFR(6)   x0 += k2; x1 += k0 + 5u;
#undef TFR
    return make_uint2(x0, x1);
}

// XLA ErfInv f32 (Giles polynomial)
__device__ __forceinline__ float erfinv_f(float x) {
    float w = -log1pf(-x * x);
    float p;
    if (w < 5.0f) {
        w -= 2.5f;
        p = 2.81022636e-08f;
        p = fmaf(p, w, 3.43273939e-07f);
        p = fmaf(p, w, -3.5233877e-06f);
        p = fmaf(p, w, -4.39150654e-06f);
        p = fmaf(p, w, 0.00021858087f);
        p = fmaf(p, w, -0.00125372503f);
        p = fmaf(p, w, -0.00417768164f);
        p = fmaf(p, w, 0.246640727f);
        p = fmaf(p, w, 1.50140941f);
    } else {
        w = sqrtf(w) - 3.0f;
        p = -0.000200214257f;
        p = fmaf(p, w, 0.000100950558f);
        p = fmaf(p, w, 0.00134934322f);
        p = fmaf(p, w, -0.00367342844f);
        p = fmaf(p, w, 0.00573950773f);
        p = fmaf(p, w, -0.0076224613f);
        p = fmaf(p, w, 0.00943887047f);
        p = fmaf(p, w, 1.00167406f);
        p = fmaf(p, w, 2.83297682f);
    }
    return p * x;
}

__device__ __forceinline__ float b2n(u32 b) {
    float f = __uint_as_float((b >> 9) | 0x3f800000u) - 1.0f;       // [0,1)
    float u = fmaxf(-0.99999994f, fmaf(f, 2.0f, -0.99999994f));
    return 1.41421356237309515f * erfinv_f(u);
}

__device__ __forceinline__ float splus(float v) {                    // logaddexp(v,0)
    return fmaxf(v, 0.0f) + log1pf(__expf(-fabsf(v)));
}
__device__ __forceinline__ float sigm(float v) {
    return __fdividef(1.0f, 1.0f + __expf(-v));
}
__device__ __forceinline__ float tanhx(float v) {
    float e = __expf(-2.0f * fabsf(v));
    float t = __fdividef(1.0f - e, 1.0f + e);
    return copysignf(t, v);
}

// ---------- prologue kernels ----------
__global__ void k_prep(const float* __restrict__ gk, const float* __restrict__ grk) {
    int i = blockIdx.x * 256 + threadIdx.x;
    if (i >= KTOT * 128) return;
    int k = i >> 7, c = i & 127;
    float wz, wr;
    if (k < UNITS) {
        wz = grk[k * G3 + c];
        wr = grk[k * G3 + 128 + c];
        g_Arh[k * 128 + c] = grk[k * G3 + 256 + c];
    } else {
        int kk = k - UNITS;
        wz = gk[kk * G3 + c];
        wr = gk[kk * G3 + 128 + c];
        g_Axh[kk * 128 + c] = gk[kk * G3 + 256 + c];
    }
    g_Azr[2 * i] = wz;
    g_Azr[2 * i + 1] = wr;
}

__global__ void k_wdec(const float* __restrict__ loc, const float* __restrict__ rho) {
    int j = blockIdx.x * 256 + threadIdx.x;
    if (j >= GAMMA * NW) return;
    uint2 kk = tf2x32(0u, 42u, 0u, 0u);             // fold_in(key(42), 0)
    uint2 o  = tf2x32(kk.x, kk.y, 0u, (u32)j);      // partitionable draw
    float n  = b2n(o.x ^ o.y);
    int jj = j % NW;
    float sc = 1e-5f + 0.02f * splus(CC + rho[jj]);
    g_wdec[j] = loc[jj] + sc * n;
}

__global__ void k_eps() {
    int j = blockIdx.x * 512 + threadIdx.x;
    if (j >= NDEC * BTOT * NF) return;
    uint2 kk = tf2x32(0u, 42u, 0u, 1u);             // fold_in(key(42), 1)
    uint2 o  = tf2x32(kk.x, kk.y, 0u, (u32)j);
    g_eps[j] = b2n(o.x ^ o.y);
}

// ---------- GRU step ----------
__device__ __forceinline__ void gru_step(float* hs, int tx, int ty,
                                         float bz, float br, float bxh, float brh) {
    const int r0 = ty * 16;
    u64 a0[8], a1[8];
#pragma unroll
    for (int j = 0; j < 8; j++) { a0[j] = 0ull; a1[j] = 0ull; }
    {
        const float2* __restrict__ wzr = reinterpret_cast<const float2*>(g_Azr) + tx;
#pragma unroll 2
        for (int k = 0; k < KTOT; k++) {
            float2 w = __ldg(&wzr[k * 128]);
            u64 wz = pk2(w.x, w.x), wr = pk2(w.y, w.y);
            const float4* hv = reinterpret_cast<const float4*>(hs + k * RP + r0);
#pragma unroll
            for (int q = 0; q < 4; q++) {
                float4 h4 = hv[q];
                u64 p = pk2(h4.x, h4.y), s = pk2(h4.z, h4.w);
                fma2(a0[2 * q], p, wz); fma2(a0[2 * q + 1], s, wz);
                fma2(a1[2 * q], p, wr); fma2(a1[2 * q + 1], s, wr);
            }
        }
    }
    float zv[16], rv[16];
#pragma unroll
    for (int j = 0; j < 8; j++) {
        float2 vz = upk2(a0[j]), vr = upk2(a1[j]);
        zv[2 * j]     = sigm(vz.x + bz);
        zv[2 * j + 1] = sigm(vz.y + bz);
        rv[2 * j]     = sigm(vr.x + br);
        rv[2 * j + 1] = sigm(vr.y + br);
    }
    // rh = h @ Wrh
#pragma unroll
    for (int j = 0; j < 8; j++) a0[j] = 0ull;
    {
        const float* __restrict__ wh = g_Arh + tx;
#pragma unroll 2
        for (int k = 0; k < UNITS; k++) {
            float w = __ldg(&wh[k * 128]);
            u64 w2 = pk2(w, w);
            const float4* hv = reinterpret_cast<const float4*>(hs + k * RP + r0);
#pragma unroll
            for (int q = 0; q < 4; q++) {
                float4 h4 = hv[q];
                fma2(a0[2 * q],     pk2(h4.x, h4.y), w2);
                fma2(a0[2 * q + 1], pk2(h4.z, h4.w), w2);
            }
        }
    }
#pragma unroll
    for (int j = 0; j < 8; j++) {
        float2 v = upk2(a0[j]);
        rv[2 * j]     *= (v.x + brh);
        rv[2 * j + 1] *= (v.y + brh);
    }
    // xh = in @ Wxh
#pragma unroll
    for (int j = 0; j < 8; j++) a0[j] = 0ull;
    {
        const float* __restrict__ wx = g_Axh + tx;
#pragma unroll 2
        for (int k = 0; k < NF; k++) {
            float w = __ldg(&wx[k * 128]);
            u64 w2 = pk2(w, w);
            const float4* hv = reinterpret_cast<const float4*>(hs + (UNITS + k) * RP + r0);
#pragma unroll
            for (int q = 0; q < 4; q++) {
                float4 h4 = hv[q];
                fma2(a0[2 * q],     pk2(h4.x, h4.y), w2);
                fma2(a0[2 * q + 1], pk2(h4.z, h4.w), w2);
            }
        }
    }
    float hh[16];
#pragma unroll
    for (int j = 0; j < 8; j++) {
        float2 v = upk2(a0[j]);
        hh[2 * j]     = tanhx(v.x + bxh + rv[2 * j]);
        hh[2 * j + 1] = tanhx(v.y + bxh + rv[2 * j + 1]);
    }
    __syncthreads();            // all accumulation reads of hs complete
    float* hc = hs + tx * RP + r0;
#pragma unroll
    for (int j = 0; j < 16; j++) {
        float ho = hc[j];       // own column: only this thread touches it
        hc[j] = zv[j] * ho + (1.0f - zv[j]) * hh[j];
    }
    __syncthreads();
}

// ---------- readout: t = h @ Kg + bg ----------
__device__ __forceinline__ void readout(const float* hs, float* ts, int g, int tx, int ty) {
    if (tx >= OUTD) return;
    const int r0 = ty * 16;
    u64 acc[8];
#pragma unroll
    for (int j = 0; j < 8; j++) acc[j] = 0ull;
    const float* __restrict__ wk = g_wdec + g * NW;
#pragma unroll 2
    for (int k = 0; k < UNITS; k++) {
        float w = __ldg(&wk[k * OUTD + tx]);
        u64 w2 = pk2(w, w);
        const float4* hv = reinterpret_cast<const float4*>(hs + k * RP + r0);
#pragma unroll
        for (int q = 0; q < 4; q++) {
            float4 h4 = hv[q];
            fma2(acc[2 * q],     pk2(h4.x, h4.y), w2);
            fma2(acc[2 * q + 1], pk2(h4.z, h4.w), w2);
        }
    }
    float bias = __ldg(&wk[KW + tx]);
    float* tc = ts + tx * TSP + r0;
#pragma unroll
    for (int j = 0; j < 8; j++) {
        float2 v = upk2(acc[j]);
        tc[2 * j]     = v.x + bias;
        tc[2 * j + 1] = v.y + bias;
    }
}

// ---------- main persistent kernel ----------
__global__ void __launch_bounds__(512, 1)
irnn_main(const float* __restrict__ x, const float* __restrict__ gb,
          float* __restrict__ out) {
    extern __shared__ float sm[];
    float* hs = sm;                    // [KTOT][RP]
    float* ts = sm + KTOT * RP;        // [OUTD][TSP]
    const int tid = threadIdx.x;
    const int tx = tid & 127, ty = tid >> 7;
    const int b0 = blockIdx.x * ROWS;

    const float bz  = gb[tx] + gb[G3 + tx];
    const float br  = gb[128 + tx] + gb[G3 + 128 + tx];
    const float bxh = gb[256 + tx];
    const float brh = gb[G3 + 256 + tx];

    for (int i = tid; i < UNITS * RP; i += 512) hs[i] = 0.0f;
    __syncthreads();

    // ---- encoder: 50 steps ----
    for (int t = 0; t < TENC; t++) {
        for (int i = tid; i < ROWS * NF; i += 512) {
            int rr = i / NF, f = i - rr * NF;
            hs[(UNITS + f) * RP + rr] = x[(size_t)(b0 + rr) * (TSEQ * NF) + t * NF + f];
        }
        __syncthreads();
        gru_step(hs, tx, ty, bz, br, bxh, brh);
    }

    // ---- readouts + decoder ----
    for (int g = 0; g < GAMMA; g++) {
        readout(hs, ts, g, tx, ty);
        __syncthreads();
        for (int i = tid; i < ROWS * OUTD; i += 512) {
            int rr = i / OUTD, j = i - rr * OUTD;
            float v = ts[j * TSP + rr];
            if (j >= NF) v = 1e-5f + 0.05f * splus(CC + v);
            out[(size_t)(b0 + rr) * (GAMMA * OUTD) + g * OUTD + j] = v;
        }
        if (g == GAMMA - 1) break;
        __syncthreads();
        for (int i = tid; i < ROWS * NF; i += 512) {
            int rr = i / NF, f = i - rr * NF;
            float loc = ts[f * TSP + rr];
            float sc = 1e-5f + 0.05f * splus(CC + ts[(NF + f) * TSP + rr]);
            float e = g_eps[((size_t)g * BTOT + b0 + rr) * NF + f];
            hs[(UNITS + f) * RP + rr] = loc + sc * e;
        }
        __syncthreads();
        gru_step(hs, tx, ty, bz, br, bxh, brh);
    }
}

// ---------- launcher ----------
extern "C" void kernel_launch(void* const* d_in, const int* in_sizes, int n_in,
                              void* d_out, int out_size) {
    const float* x   = (const float*)d_in[0];
    const float* gk  = (const float*)d_in[1];
    const float* grk = (const float*)d_in[2];
    const float* gb  = (const float*)d_in[3];
    const float* pl  = (const float*)d_in[4];
    const float* pr  = (const float*)d_in[5];
    float* out = (float*)d_out;

    cudaFuncSetAttribute(irnn_main, cudaFuncAttributeMaxDynamicSharedMemorySize,
                         SMFLOATS * (int)sizeof(float));

    k_prep<<<(KTOT * 128 + 255) / 256, 256>>>(gk, grk);
    k_wdec<<<(GAMMA * NW + 255) / 256, 256>>>(pl, pr);
    k_eps<<<(NDEC * BTOT * NF + 511) / 512, 512>>>();
    irnn_main<<<BTOT / ROWS, 512, SMFLOATS * sizeof(float)>>>(x, gb, out);
}

// round 4
// speedup vs baseline: 1.4782x; 1.4782x over previous
#include <cuda_runtime.h>
#include <cstdint>

#define NF     51
#define UNITS  128
#define G3     384
#define TENC   50
#define NDEC   27
#define GAMMA  28
#define OUTD   102
#define KW     13056          // UNITS*OUTD
#define NW     13158
#define BTOT   8192
#define TSEQ   64
#define ROWS   64
#define RP     68             // padded row stride (floats)
#define KTOT   179            // 128 h + 51 input
#define TSP    65             // ts stride
#define CC     0.5413248546129181f

#define SMFLOATS (KTOT*RP + OUTD*TSP)

__device__ __align__(16) float4 g_Wf[KTOT * 128];     // (Wz, Wr, Wh, 0) per [k][col]
__device__ __align__(16) float  g_wdec[GAMMA * NW];
__device__ __align__(16) float  g_eps[NDEC * BTOT * NF];

typedef unsigned long long u64;
typedef unsigned int u32;

// ---------- f32x2 helpers ----------
__device__ __forceinline__ u64 pk2(float lo, float hi) {
    u64 r; asm("mov.b64 %0, {%1, %2};" : "=l"(r) : "f"(lo), "f"(hi)); return r;
}
__device__ __forceinline__ float2 upk2(u64 v) {
    float2 f; asm("mov.b64 {%0, %1}, %2;" : "=f"(f.x), "=f"(f.y) : "l"(v)); return f;
}
__device__ __forceinline__ void fma2(u64& d, u64 a, u64 b) {
    asm("fma.rn.f32x2 %0, %1, %2, %0;" : "+l"(d) : "l"(a), "l"(b));
}

// ---------- JAX threefry2x32 (exact) ----------
__device__ __forceinline__ uint2 tf2x32(u32 k0, u32 k1, u32 x0, u32 x1) {
    u32 k2 = k0 ^ k1 ^ 0x1BD11BDAu;
#define TFR(r) { x0 += x1; x1 = (x1 << (r)) | (x1 >> (32 - (r))); x1 ^= x0; }
    x0 += k0; x1 += k1;
    TFR(13) TFR(15) TFR(26) TFR(6)   x0 += k1; x1 += k2 + 1u;
    TFR(17) TFR(29) TFR(16) TFR(24)  x0 += k2; x1 += k0 + 2u;
    TFR(13) TFR(15) TFR(26) TFR(6)   x0 += k0; x1 += k1 + 3u;
    TFR(17) TFR(29) TFR(16) TFR(24)  x0 += k1; x1 += k2 + 4u;
    TFR(13) TFR(15) TFR(26) TFR(6)   x0 += k2; x1 += k0 + 5u;
#undef TFR
    return make_uint2(x0, x1);
}

// XLA ErfInv f32 (Giles polynomial)
__device__ __forceinline__ float erfinv_f(float x) {
    float w = -log1pf(-x * x);
    float p;
    if (w < 5.0f) {
        w -= 2.5f;
        p = 2.81022636e-08f;
        p = fmaf(p, w, 3.43273939e-07f);
        p = fmaf(p, w, -3.5233877e-06f);
        p = fmaf(p, w, -4.39150654e-06f);
        p = fmaf(p, w, 0.00021858087f);
        p = fmaf(p, w, -0.00125372503f);
        p = fmaf(p, w, -0.00417768164f);
        p = fmaf(p, w, 0.246640727f);
        p = fmaf(p, w, 1.50140941f);
    } else {
        w = sqrtf(w) - 3.0f;
        p = -0.000200214257f;
        p = fmaf(p, w, 0.000100950558f);
        p = fmaf(p, w, 0.00134934322f);
        p = fmaf(p, w, -0.00367342844f);
        p = fmaf(p, w, 0.00573950773f);
        p = fmaf(p, w, -0.0076224613f);
        p = fmaf(p, w, 0.00943887047f);
        p = fmaf(p, w, 1.00167406f);
        p = fmaf(p, w, 2.83297682f);
    }
    return p * x;
}

__device__ __forceinline__ float b2n(u32 b) {
    float f = __uint_as_float((b >> 9) | 0x3f800000u) - 1.0f;       // [0,1)
    float u = fmaxf(-0.99999994f, fmaf(f, 2.0f, -0.99999994f));
    return 1.41421356237309515f * erfinv_f(u);
}

__device__ __forceinline__ float splus(float v) {                    // logaddexp(v,0)
    return fmaxf(v, 0.0f) + log1pf(__expf(-fabsf(v)));
}
__device__ __forceinline__ float sigm(float v) {
    return __fdividef(1.0f, 1.0f + __expf(-v));
}
__device__ __forceinline__ float tanhx(float v) {
    float e = __expf(-2.0f * fabsf(v));
    float t = __fdividef(1.0f - e, 1.0f + e);
    return copysignf(t, v);
}

// ---------- prologue kernels ----------
__global__ void k_prep(const float* __restrict__ gk, const float* __restrict__ grk) {
    int i = blockIdx.x * 256 + threadIdx.x;
    if (i >= KTOT * 128) return;
    int k = i >> 7, c = i & 127;
    float wz, wr, wh;
    if (k < UNITS) {
        wz = grk[k * G3 + c];
        wr = grk[k * G3 + 128 + c];
        wh = grk[k * G3 + 256 + c];
    } else {
        int f = k - UNITS;
        wz = gk[f * G3 + c];
        wr = gk[f * G3 + 128 + c];
        wh = gk[f * G3 + 256 + c];
    }
    g_Wf[i] = make_float4(wz, wr, wh, 0.0f);
}

__global__ void k_wdec(const float* __restrict__ loc, const float* __restrict__ rho) {
    int j = blockIdx.x * 256 + threadIdx.x;
    if (j >= GAMMA * NW) return;
    uint2 kk = tf2x32(0u, 42u, 0u, 0u);             // fold_in(key(42), 0)
    uint2 o  = tf2x32(kk.x, kk.y, 0u, (u32)j);      // partitionable draw
    float n  = b2n(o.x ^ o.y);
    int jj = j % NW;
    float sc = 1e-5f + 0.02f * splus(CC + rho[jj]);
    g_wdec[j] = loc[jj] + sc * n;
}

__global__ void k_eps() {
    int j = blockIdx.x * 512 + threadIdx.x;
    if (j >= NDEC * BTOT * NF) return;
    uint2 kk = tf2x32(0u, 42u, 0u, 1u);             // fold_in(key(42), 1)
    uint2 o  = tf2x32(kk.x, kk.y, 0u, (u32)j);
    g_eps[j] = b2n(o.x ^ o.y);
}

// ---------- fused GRU step ----------
// Single pass over k: each k feeds z, r and (rh | xh) accumulators.
__device__ __forceinline__ void gru_step(float* hs, int tx, int ty,
                                         float bz, float br, float bxh, float brh) {
    const int r0 = ty * 16;
    u64 az[8], ar[8], ahr[8], ahx[8];
#pragma unroll
    for (int j = 0; j < 8; j++) { az[j] = 0ull; ar[j] = 0ull; ahr[j] = 0ull; ahx[j] = 0ull; }

    const float4* __restrict__ Wp = g_Wf + tx;

    // ---- phase 1: k = 0..127 (hidden state), accumulate az, ar, ahr ----
    {
        float4 w0 = __ldg(&Wp[0]);
        float4 w1 = __ldg(&Wp[128]);
#pragma unroll 2
        for (int k = 0; k < UNITS; k++) {
            float4 wc = w0;
            w0 = w1;
            w1 = __ldg(&Wp[(k + 2) * 128]);           // k+2 <= 129 < KTOT, always valid
            const float4* hv = reinterpret_cast<const float4*>(hs + k * RP + r0);
            float4 a = hv[0], b = hv[1], c = hv[2], d = hv[3];
            u64 wz = pk2(wc.x, wc.x), wr = pk2(wc.y, wc.y), wh = pk2(wc.z, wc.z);
            u64 p0 = pk2(a.x, a.y), p1 = pk2(a.z, a.w);
            u64 p2 = pk2(b.x, b.y), p3 = pk2(b.z, b.w);
            u64 p4 = pk2(c.x, c.y), p5 = pk2(c.z, c.w);
            u64 p6 = pk2(d.x, d.y), p7 = pk2(d.z, d.w);
            fma2(az[0], p0, wz); fma2(az[1], p1, wz); fma2(az[2], p2, wz); fma2(az[3], p3, wz);
            fma2(az[4], p4, wz); fma2(az[5], p5, wz); fma2(az[6], p6, wz); fma2(az[7], p7, wz);
            fma2(ar[0], p0, wr); fma2(ar[1], p1, wr); fma2(ar[2], p2, wr); fma2(ar[3], p3, wr);
            fma2(ar[4], p4, wr); fma2(ar[5], p5, wr); fma2(ar[6], p6, wr); fma2(ar[7], p7, wr);
            fma2(ahr[0], p0, wh); fma2(ahr[1], p1, wh); fma2(ahr[2], p2, wh); fma2(ahr[3], p3, wh);
            fma2(ahr[4], p4, wh); fma2(ahr[5], p5, wh); fma2(ahr[6], p6, wh); fma2(ahr[7], p7, wh);
        }
    }
    // ---- phase 2: k = 128..178 (input), accumulate az, ar, ahx ----
    {
        float4 w0 = __ldg(&Wp[UNITS * 128]);
        float4 w1 = __ldg(&Wp[(UNITS + 1) * 128]);
#pragma unroll 2
        for (int k = UNITS; k < KTOT; k++) {
            float4 wc = w0;
            w0 = w1;
            int kn = k + 2 < KTOT ? k + 2 : KTOT - 1;
            w1 = __ldg(&Wp[kn * 128]);
            const float4* hv = reinterpret_cast<const float4*>(hs + k * RP + r0);
            float4 a = hv[0], b = hv[1], c = hv[2], d = hv[3];
            u64 wz = pk2(wc.x, wc.x), wr = pk2(wc.y, wc.y), wh = pk2(wc.z, wc.z);
            u64 p0 = pk2(a.x, a.y), p1 = pk2(a.z, a.w);
            u64 p2 = pk2(b.x, b.y), p3 = pk2(b.z, b.w);
            u64 p4 = pk2(c.x, c.y), p5 = pk2(c.z, c.w);
            u64 p6 = pk2(d.x, d.y), p7 = pk2(d.z, d.w);
            fma2(az[0], p0, wz); fma2(az[1], p1, wz); fma2(az[2], p2, wz); fma2(az[3], p3, wz);
            fma2(az[4], p4, wz); fma2(az[5], p5, wz); fma2(az[6], p6, wz); fma2(az[7], p7, wz);
            fma2(ar[0], p0, wr); fma2(ar[1], p1, wr); fma2(ar[2], p2, wr); fma2(ar[3], p3, wr);
            fma2(ar[4], p4, wr); fma2(ar[5], p5, wr); fma2(ar[6], p6, wr); fma2(ar[7], p7, wr);
            fma2(ahx[0], p0, wh); fma2(ahx[1], p1, wh); fma2(ahx[2], p2, wh); fma2(ahx[3], p3, wh);
            fma2(ahx[4], p4, wh); fma2(ahx[5], p5, wh); fma2(ahx[6], p6, wh); fma2(ahx[7], p7, wh);
        }
    }
    // ---- epilogue ----
    float zv[16], hhv[16];
#pragma unroll
    for (int j = 0; j < 8; j++) {
        float2 vz = upk2(az[j]), vr = upk2(ar[j]);
        float2 vhr = upk2(ahr[j]), vhx = upk2(ahx[j]);
        float z0 = sigm(vz.x + bz), z1 = sigm(vz.y + bz);
        float q0 = sigm(vr.x + br), q1 = sigm(vr.y + br);
        zv[2 * j]     = z0;
        zv[2 * j + 1] = z1;
        hhv[2 * j]     = tanhx(vhx.x + bxh + q0 * (vhr.x + brh));
        hhv[2 * j + 1] = tanhx(vhx.y + bxh + q1 * (vhr.y + brh));
    }
    __syncthreads();            // all reads of hs complete
    float* hc = hs + tx * RP + r0;
#pragma unroll
    for (int j = 0; j < 16; j++) {
        float ho = hc[j];       // own column: only this thread touches it
        hc[j] = zv[j] * ho + (1.0f - zv[j]) * hhv[j];
    }
    __syncthreads();
}

// ---------- readout: t = h @ Kg + bg ----------
__device__ __forceinline__ void readout(const float* hs, float* ts, int g, int tx, int ty) {
    if (tx >= OUTD) return;
    const int r0 = ty * 16;
    u64 acc[8];
#pragma unroll
    for (int j = 0; j < 8; j++) acc[j] = 0ull;
    const float* __restrict__ wk = g_wdec + g * NW;
    float w0 = __ldg(&wk[tx]);
    float w1 = __ldg(&wk[OUTD + tx]);
#pragma unroll 2
    for (int k = 0; k < UNITS; k++) {
        float w = w0;
        w0 = w1;
        int kn = k + 2 < UNITS ? k + 2 : UNITS - 1;
        w1 = __ldg(&wk[kn * OUTD + tx]);
        u64 w2 = pk2(w, w);
        const float4* hv = reinterpret_cast<const float4*>(hs + k * RP + r0);
#pragma unroll
        for (int q = 0; q < 4; q++) {
            float4 h4 = hv[q];
            fma2(acc[2 * q],     pk2(h4.x, h4.y), w2);
            fma2(acc[2 * q + 1], pk2(h4.z, h4.w), w2);
        }
    }
    float bias = __ldg(&wk[KW + tx]);
    float* tc = ts + tx * TSP + r0;
#pragma unroll
    for (int j = 0; j < 8; j++) {
        float2 v = upk2(acc[j]);
        tc[2 * j]     = v.x + bias;
        tc[2 * j + 1] = v.y + bias;
    }
}

// ---------- main persistent kernel ----------
__global__ void __launch_bounds__(512, 1)
irnn_main(const float* __restrict__ x, const float* __restrict__ gb,
          float* __restrict__ out) {
    extern __shared__ float sm[];
    float* hs = sm;                    // [KTOT][RP]
    float* ts = sm + KTOT * RP;        // [OUTD][TSP]
    const int tid = threadIdx.x;
    const int tx = tid & 127, ty = tid >> 7;
    const int b0 = blockIdx.x * ROWS;

    const float bz  = gb[tx] + gb[G3 + tx];
    const float br  = gb[128 + tx] + gb[G3 + 128 + tx];
    const float bxh = gb[256 + tx];
    const float brh = gb[G3 + 256 + tx];

    for (int i = tid; i < UNITS * RP; i += 512) hs[i] = 0.0f;
    __syncthreads();

    // ---- encoder: 50 steps ----
    for (int t = 0; t < TENC; t++) {
        for (int i = tid; i < ROWS * NF; i += 512) {
            int rr = i / NF, f = i - rr * NF;
            hs[(UNITS + f) * RP + rr] = __ldg(&x[(size_t)(b0 + rr) * (TSEQ * NF) + t * NF + f]);
        }
        __syncthreads();
        gru_step(hs, tx, ty, bz, br, bxh, brh);
    }

    // ---- readouts + decoder ----
    for (int g = 0; g < GAMMA; g++) {
        readout(hs, ts, g, tx, ty);
        __syncthreads();
        for (int i = tid; i < ROWS * OUTD; i += 512) {
            int rr = i / OUTD, j = i - rr * OUTD;
            float v = ts[j * TSP + rr];
            if (j >= NF) v = 1e-5f + 0.05f * splus(CC + v);
            out[(size_t)(b0 + rr) * (GAMMA * OUTD) + g * OUTD + j] = v;
        }
        if (g == GAMMA - 1) break;
        __syncthreads();
        for (int i = tid; i < ROWS * NF; i += 512) {
            int rr = i / NF, f = i - rr * NF;
            float loc = ts[f * TSP + rr];
            float sc = 1e-5f + 0.05f * splus(CC + ts[(NF + f) * TSP + rr]);
            float e = g_eps[((size_t)g * BTOT + b0 + rr) * NF + f];
            hs[(UNITS + f) * RP + rr] = loc + sc * e;
        }
        __syncthreads();
        gru_step(hs, tx, ty, bz, br, bxh, brh);
    }
}

// ---------- launcher ----------
extern "C" void kernel_launch(void* const* d_in, const int* in_sizes, int n_in,
                              void* d_out, int out_size) {
    const float* x   = (const float*)d_in[0];
    const float* gk  = (const float*)d_in[1];
    const float* grk = (const float*)d_in[2];
    const float* gb  = (const float*)d_in[3];
    const float* pl  = (const float*)d_in[4];
    const float* pr  = (const float*)d_in[5];
    float* out = (float*)d_out;

    cudaFuncSetAttribute(irnn_main, cudaFuncAttributeMaxDynamicSharedMemorySize,
                         SMFLOATS * (int)sizeof(float));

    k_prep<<<(KTOT * 128 + 255) / 256, 256>>>(gk, grk);
    k_wdec<<<(GAMMA * NW + 255) / 256, 256>>>(pl, pr);
    k_eps<<<(NDEC * BTOT * NF + 511) / 512, 512>>>();
    irnn_main<<<BTOT / ROWS, 512, SMFLOATS * sizeof(float)>>>(x, gb, out);
}